// round 4
// baseline (speedup 1.0000x reference)
#include <cuda_runtime.h>
#include <math_constants.h>
#include <stdint.h>

#define BATCH 8
#define CH 256
#define HH 128
#define WW 128
#define HWSZ 16384
#define NPTS 500
#define NPAD 512
#define NHID 16

typedef unsigned long long u64;

// ---------------- scratch ----------------
__device__ float g_score[BATCH * HWSZ];
__device__ int   g_idx[BATCH * NPTS];
__device__ float g_vmt [BATCH * CH * NPAD];   // v_main transposed [b][c][n], zero-padded
__device__ float g_vat [BATCH * CH * NPAD];   // v_aux  transposed [b][c][n]
__device__ float g_vaux[BATCH * NPTS * CH];   // v_aux row-major [b][n][c]

// ---------------- f32x2 helpers ----------------
__device__ __forceinline__ u64 pk2(float x, float y) {
    u64 d; asm("mov.b64 %0, {%1, %2};" : "=l"(d) : "f"(x), "f"(y)); return d;
}
__device__ __forceinline__ void upk2(float& x, float& y, u64 d) {
    asm("mov.b64 {%0, %1}, %2;" : "=f"(x), "=f"(y) : "l"(d));
}
__device__ __forceinline__ u64 f2fma(u64 a, u64 b, u64 c) {
    u64 d; asm("fma.rn.f32x2 %0, %1, %2, %3;" : "=l"(d) : "l"(a), "l"(b), "l"(c)); return d;
}
__device__ __forceinline__ u64 f2mul(u64 a, u64 b) {
    u64 d; asm("mul.rn.f32x2 %0, %1, %2;" : "=l"(d) : "l"(a), "l"(b)); return d;
}

// ================= kernel 1: fused copy + scorer, block-local reduce =================
// Block = 32 pixel-quads (128 px); warp w owns channels [32w,32w+32); smem reduce.
__global__ void __launch_bounds__(256) k1_copy_score(const float* __restrict__ xm,
                                                     const float* __restrict__ sw,
                                                     float* __restrict__ out) {
    __shared__ float s_w[CH];
    __shared__ float4 part[8][32];
    int t = threadIdx.x, lane = t & 31, w = t >> 5;
    s_w[t] = sw[t];
    __syncthreads();

    int q  = blockIdx.x * 32 + lane;          // quad id
    int gp = q * 4;
    int b  = gp >> 14;
    int hw = gp & (HWSZ - 1);
    const float4* src = reinterpret_cast<const float4*>(xm + (size_t)(b * CH + 32 * w) * HWSZ + hw);
    float4*       dst = reinterpret_cast<float4*>(out + (size_t)(b * CH + 32 * w) * HWSZ + hw);

    float a0 = 0.f, a1 = 0.f, a2 = 0.f, a3 = 0.f;
    #pragma unroll 8
    for (int i = 0; i < 32; ++i) {
        float4 v = src[i * (HWSZ / 4)];
        dst[i * (HWSZ / 4)] = v;
        float wt = s_w[32 * w + i];
        a0 += v.x * wt; a1 += v.y * wt; a2 += v.z * wt; a3 += v.w * wt;
    }
    part[w][lane] = make_float4(a0, a1, a2, a3);
    __syncthreads();
    if (w == 0) {
        float4 s = part[0][lane];
        #pragma unroll
        for (int r = 1; r < 8; ++r) {
            float4 v = part[r][lane];
            s.x += v.x; s.y += v.y; s.z += v.z; s.w += v.w;
        }
        *reinterpret_cast<float4*>(g_score + gp) = s;
    }
}

// ================= kernel 2: exact top-500 per batch via radix select =================
__global__ void k2_topk() {
    __shared__ unsigned hist[256];
    __shared__ unsigned sh_pref;
    __shared__ int sh_k;
    __shared__ int cntGT, eqcnt;
    __shared__ int eqbuf[1024];

    int b = blockIdx.x, t = threadIdx.x, bd = blockDim.x;
    const float* sc = g_score + b * HWSZ;

    unsigned prefix = 0;
    int k = NPTS;
    for (int byte = 3; byte >= 0; --byte) {
        if (t < 256) hist[t] = 0;
        __syncthreads();
        int shamt = byte * 8;
        for (int i = t; i < HWSZ; i += bd) {
            unsigned u = __float_as_uint(sc[i]);
            u = (u & 0x80000000u) ? ~u : (u | 0x80000000u);
            bool m = (byte == 3) || ((u >> (shamt + 8)) == prefix);
            if (m) atomicAdd(&hist[(u >> shamt) & 255u], 1u);
        }
        __syncthreads();
        if (t == 0) {
            int cum = 0, bin;
            for (bin = 255; bin >= 0; --bin) {
                int h = (int)hist[bin];
                if (cum + h >= k) break;
                cum += h;
            }
            if (bin < 0) bin = 0;
            sh_pref = (prefix << 8) | (unsigned)bin;
            sh_k = k - cum;
        }
        __syncthreads();
        prefix = sh_pref; k = sh_k;
        __syncthreads();
    }
    unsigned T = prefix;
    if (t == 0) { cntGT = 0; eqcnt = 0; }
    __syncthreads();
    for (int i = t; i < HWSZ; i += bd) {
        unsigned u = __float_as_uint(sc[i]);
        u = (u & 0x80000000u) ? ~u : (u | 0x80000000u);
        if (u > T) {
            int p = atomicAdd(&cntGT, 1);
            if (p < NPTS) g_idx[b * NPTS + p] = i;
        } else if (u == T) {
            int e = atomicAdd(&eqcnt, 1);
            if (e < 1024) eqbuf[e] = i;
        }
    }
    __syncthreads();
    if (t == 0) {
        int need = k;
        int base = cntGT;
        int ec = eqcnt; if (ec > 1024) ec = 1024;
        if (ec > need) {
            for (int a = 1; a < ec; ++a) {
                int v = eqbuf[a]; int jj = a - 1;
                while (jj >= 0 && eqbuf[jj] > v) { eqbuf[jj + 1] = eqbuf[jj]; --jj; }
                eqbuf[jj + 1] = v;
            }
        }
        for (int e = 0; e < need && e < ec && base + e < NPTS; ++e)
            g_idx[b * NPTS + base + e] = eqbuf[e];
    }
}

// ================= kernel 3: persistent double-buffered plane pooling =================
// 4096 plane-tasks (b,c,src). cp.async next plane into alt buffer while pooling
// current. Plane staged with pitch 132 (132%32=4) -> patch rows hit shifted banks.
#define K3_PITCH 132
#define K3_PLANE (128 * K3_PITCH)
#define K3_NTASK (BATCH * CH * 2)
#define K3_GRID 152

__device__ __forceinline__ void k3_issue(const float* __restrict__ xm,
                                         const float* __restrict__ xa,
                                         float* sp, int task, int par, int t) {
    int src = task & 1;
    int c   = (task >> 1) & 255;
    int b   = task >> 9;
    const float* gsrc = (src == 0 ? xm : xa) + (size_t)(b * CH + c) * HWSZ;
    float* buf = sp + par * K3_PLANE;
    #pragma unroll
    for (int i = 0; i < 16; ++i) {
        int idx = t + i * 256;              // 4096 chunks of 16B
        int row = idx >> 5, col = idx & 31;
        uint32_t daddr;
        asm("{ .reg .u64 tmp; cvta.to.shared.u64 tmp, %1; cvt.u32.u64 %0, tmp; }"
            : "=r"(daddr) : "l"(buf + row * K3_PITCH + col * 4));
        asm volatile("cp.async.cg.shared.global [%0], [%1], 16;"
                     :: "r"(daddr), "l"(gsrc + row * WW + col * 4));
    }
}

__global__ void __launch_bounds__(256) k3_pool(const float* __restrict__ xm,
                                               const float* __restrict__ xa) {
    extern __shared__ float sp[];            // [2][K3_PLANE] then int s_hw[512]
    int* s_hw = (int*)(sp + 2 * K3_PLANE);
    int t = threadIdx.x, lane = t & 31, w = t >> 5;
    int nb = gridDim.x;

    // per-lane sample decomposition: s1 = lane, s2 = lane+32 (valid if <49)
    int dy1 = lane / 7, dx1 = lane - dy1 * 7;
    int s2 = lane + 32;
    bool has2 = (s2 < 49);
    int dy2 = s2 / 7, dx2 = s2 - dy2 * 7;

    int cur = blockIdx.x;
    if (cur < K3_NTASK) k3_issue(xm, xa, sp, cur, 0, t);
    asm volatile("cp.async.commit_group;");
    int par = 0;

    while (cur < K3_NTASK) {
        int nxt = cur + nb;
        if (nxt < K3_NTASK) k3_issue(xm, xa, sp, nxt, par ^ 1, t);
        asm volatile("cp.async.commit_group;");

        int src = cur & 1;
        int c   = (cur >> 1) & 255;
        int b   = cur >> 9;
        for (int i = t; i < NPTS; i += 256) s_hw[i] = g_idx[b * NPTS + i];

        asm volatile("cp.async.wait_group 1;");
        __syncthreads();

        const float* pl = sp + par * K3_PLANE;
        for (int p = w; p < NPTS; p += 8) {
            int hw = s_hw[p];
            int iy = hw >> 7, ix = hw & 127;
            float v1, v2s, v2m;
            if (iy >= 3 && iy <= 124 && ix >= 3 && ix <= 124) {
                const float* bse = pl + (iy - 3) * K3_PITCH + (ix - 3);
                v1 = bse[dy1 * K3_PITCH + dx1];
                float v2 = has2 ? bse[dy2 * K3_PITCH + dx2] : 0.f;
                v2s = has2 ? v2 : 0.f;
                v2m = has2 ? v2 : -CUDART_INF_F;
            } else {
                int y1 = iy + dy1 - 3, x1 = ix + dx1 - 3;
                float w1 = 1.f;
                if (y1 < 0) { y1 = 0; w1 = 0.5f; } else if (y1 > 127) { y1 = 127; w1 = 0.5f; }
                if (x1 < 0) { x1 = 0; w1 *= 0.5f; } else if (x1 > 127) { x1 = 127; w1 *= 0.5f; }
                v1 = pl[y1 * K3_PITCH + x1] * w1;
                if (has2) {
                    int y2 = iy + dy2 - 3, x2 = ix + dx2 - 3;
                    float w2 = 1.f;
                    if (y2 < 0) { y2 = 0; w2 = 0.5f; } else if (y2 > 127) { y2 = 127; w2 = 0.5f; }
                    if (x2 < 0) { x2 = 0; w2 *= 0.5f; } else if (x2 > 127) { x2 = 127; w2 *= 0.5f; }
                    float v2 = pl[y2 * K3_PITCH + x2] * w2;
                    v2s = v2; v2m = v2;
                } else { v2s = 0.f; v2m = -CUDART_INF_F; }
            }
            float sum = v1 + v2s;
            float mx  = fmaxf(v1, v2m);
            #pragma unroll
            for (int o = 16; o; o >>= 1) {
                sum += __shfl_xor_sync(0xffffffffu, sum, o);
                mx = fmaxf(mx, __shfl_xor_sync(0xffffffffu, mx, o));
            }
            if (lane == 0) {
                float r = 0.5f * (sum * (1.f / 49.f) + mx);
                if (src == 0) {
                    g_vmt[(b * CH + c) * NPAD + p] = r;
                } else {
                    g_vat[(b * CH + c) * NPAD + p] = r;
                    g_vaux[(b * NPTS + p) * CH + c] = r;
                }
            }
        }
        __syncthreads();
        cur = nxt; par ^= 1;
    }
}

// ================= kernel 4: attention + gated MLP + proj + scatter (f32x2) =================
#define SM_QS 0
#define SM_T  9216
#define SM_S  18432
#define SM_VH 36864
#define SM_TOT 45184

__global__ void __launch_bounds__(256, 1)
k4_attn(const float* __restrict__ fc1w, const float* __restrict__ fc1b,
        const float* __restrict__ fc2w, const float* __restrict__ fc2b,
        const float* __restrict__ pw,   const float* __restrict__ pb,
        float* __restrict__ out) {
    extern __shared__ float sm[];
    float* Qs  = sm + SM_QS;
    float* T   = sm + SM_T;
    float* S_t = sm + SM_S;
    float* Vh  = sm + SM_VH;

    const int t  = threadIdx.x;
    const int tx = t & 31, ty = t >> 5;
    const int b  = blockIdx.y;
    const int r0 = blockIdx.x * 32;
    const int nrows = min(32, NPTS - r0);

    for (int idx4 = t; idx4 < 2048; idx4 += 256) {
        int k = idx4 >> 3, i4 = (idx4 & 7) * 4;
        float4 v = *reinterpret_cast<const float4*>(&g_vmt[(b * CH + k) * NPAD + r0 + i4]);
        *reinterpret_cast<float4*>(&Qs[k * 36 + i4]) = v;
    }
    __syncthreads();

    for (int mt = 0; mt < 16; ++mt) {
        int m0 = mt * 32;
        for (int idx4 = t; idx4 < 2048; idx4 += 256) {
            int k = idx4 >> 3, i4 = (idx4 & 7) * 4;
            float4 v = *reinterpret_cast<const float4*>(&g_vat[(b * CH + k) * NPAD + m0 + i4]);
            *reinterpret_cast<float4*>(&T[k * 36 + i4]) = v;
        }
        __syncthreads();
        u64 s01 = pk2(0.f, 0.f), s23 = pk2(0.f, 0.f);
        #pragma unroll 8
        for (int k = 0; k < 256; ++k) {
            ulonglong2 q = *reinterpret_cast<const ulonglong2*>(&Qs[k * 36 + 4 * ty]);
            float kk = T[k * 36 + tx];
            u64 kk2 = pk2(kk, kk);
            s01 = f2fma(q.x, kk2, s01);
            s23 = f2fma(q.y, kk2, s23);
        }
        float a0, a1, a2, a3;
        upk2(a0, a1, s01); upk2(a2, a3, s23);
        *reinterpret_cast<float4*>(&S_t[(m0 + tx) * 36 + 4 * ty]) =
            make_float4(a0 * 0.0625f, a1 * 0.0625f, a2 * 0.0625f, a3 * 0.0625f);
        __syncthreads();
    }

    float inv[4];
    #pragma unroll
    for (int i = 0; i < 4; ++i) {
        int r = 4 * ty + i;
        float mx = -CUDART_INF_F;
        for (int m = tx; m < NPTS; m += 32) mx = fmaxf(mx, S_t[m * 36 + r]);
        #pragma unroll
        for (int o = 16; o; o >>= 1) mx = fmaxf(mx, __shfl_xor_sync(0xffffffffu, mx, o));
        float sum = 0.f;
        for (int m = tx; m < NPTS; m += 32) {
            float e = __expf(S_t[m * 36 + r] - mx);
            S_t[m * 36 + r] = e;
            sum += e;
        }
        #pragma unroll
        for (int o = 16; o; o >>= 1) sum += __shfl_xor_sync(0xffffffffu, sum, o);
        inv[i] = 1.f / sum;
    }
    __syncthreads();

    u64 acc[4][4];
    #pragma unroll
    for (int i = 0; i < 4; ++i)
        #pragma unroll
        for (int j = 0; j < 4; ++j) acc[i][j] = pk2(0.f, 0.f);

    for (int mt = 0; mt < 16; ++mt) {
        int m0 = mt * 32;
        int mlim = min(32, NPTS - m0);
        for (int idx4 = t; idx4 < 2048; idx4 += 256) {
            int m = idx4 >> 6, c4 = (idx4 & 63) * 4;
            float4 v = make_float4(0.f, 0.f, 0.f, 0.f);
            if (m < mlim)
                v = *reinterpret_cast<const float4*>(&g_vaux[(b * NPTS + m0 + m) * CH + c4]);
            *reinterpret_cast<float4*>(&T[m * 260 + c4]) = v;
        }
        __syncthreads();
        for (int m = 0; m < mlim; ++m) {
            ulonglong2 pp = *reinterpret_cast<const ulonglong2*>(&S_t[(m0 + m) * 36 + 4 * ty]);
            float p0, p1, p2, p3;
            upk2(p0, p1, pp.x); upk2(p2, p3, pp.y);
            u64 a0 = pk2(p0, p0), a1 = pk2(p1, p1), a2 = pk2(p2, p2), a3 = pk2(p3, p3);
            #pragma unroll
            for (int j = 0; j < 4; ++j) {
                u64 v = *reinterpret_cast<const u64*>(&T[m * 260 + 64 * j + 2 * tx]);
                acc[0][j] = f2fma(a0, v, acc[0][j]);
                acc[1][j] = f2fma(a1, v, acc[1][j]);
                acc[2][j] = f2fma(a2, v, acc[2][j]);
                acc[3][j] = f2fma(a3, v, acc[3][j]);
            }
        }
        __syncthreads();
    }
    #pragma unroll
    for (int i = 0; i < 4; ++i) {
        u64 s = pk2(inv[i], inv[i]);
        #pragma unroll
        for (int j = 0; j < 4; ++j)
            *reinterpret_cast<u64*>(&Vh[(4 * ty + i) * 260 + 64 * j + 2 * tx]) =
                f2mul(acc[i][j], s);
    }
    __syncthreads();

    float* W1p  = T;
    float* Vf_t = S_t;
    float* W2s  = S_t + 9216;
    for (int idx = t; idx < 256 * 16; idx += 256) {
        int k = idx >> 4, j = idx & 15;
        float wa = fc1w[idx];
        float wb = fc1w[4096 + idx];
        float wc = fc1w[8192 + idx];
        W1p[k * 32 + 2 * j]     = wa + wc;
        W1p[k * 32 + 2 * j + 1] = wb - wc;
    }
    for (int idx = t; idx < 4096; idx += 256) W2s[idx] = fc2w[idx];
    __syncthreads();

    int jl = tx & 15, half = tx >> 4;
    float hreg[4];
    #pragma unroll
    for (int i = 0; i < 4; ++i) {
        int r = 4 * ty + i;
        u64 hp = pk2(0.f, 0.f);
        int k0 = half * 128;
        #pragma unroll 4
        for (int k = k0; k < k0 + 128; ++k) {
            float vm = Qs[k * 36 + r];
            float vh = Vh[r * 260 + k];
            u64 w = *reinterpret_cast<const u64*>(&W1p[k * 32 + 2 * jl]);
            hp = f2fma(pk2(vm, vh), w, hp);
        }
        float hx, hy; upk2(hx, hy, hp);
        float h = hx + hy;
        h += __shfl_xor_sync(0xffffffffu, h, 16);
        h += fc1b[jl];
        hreg[i] = fmaxf(h, 0.f);
    }

    #pragma unroll
    for (int i = 0; i < 4; ++i) {
        int r = 4 * ty + i;
        for (int cb = 0; cb < 256; cb += 32) {
            int c = cb + tx;
            float g = fc2b[c];
            #pragma unroll
            for (int jj = 0; jj < 16; ++jj) {
                float hj = __shfl_sync(0xffffffffu, hreg[i], jj);
                g += hj * W2s[jj * 256 + c];
            }
            g = 1.f / (1.f + __expf(-g));
            float vm = Qs[c * 36 + r];
            float vh = Vh[r * 260 + c];
            Vf_t[c * 36 + r] = vm + g * (vm - vh);
        }
    }
    __syncthreads();

    float* Pw = T;
    u64 pacc[4][4];
    #pragma unroll
    for (int i = 0; i < 4; ++i)
        #pragma unroll
        for (int j = 0; j < 4; ++j) pacc[i][j] = pk2(0.f, 0.f);

    for (int kt = 0; kt < 8; ++kt) {
        int k0 = kt * 32;
        for (int idx4 = t; idx4 < 2048; idx4 += 256) {
            int kk = idx4 >> 6, c4 = (idx4 & 63) * 4;
            float4 v = *reinterpret_cast<const float4*>(&pw[(k0 + kk) * 256 + c4]);
            *reinterpret_cast<float4*>(&Pw[kk * 260 + c4]) = v;
        }
        __syncthreads();
        for (int kk = 0; kk < 32; ++kk) {
            ulonglong2 ff = *reinterpret_cast<const ulonglong2*>(&Vf_t[(k0 + kk) * 36 + 4 * ty]);
            float f0, f1, f2, f3;
            upk2(f0, f1, ff.x); upk2(f2, f3, ff.y);
            u64 a0 = pk2(f0, f0), a1 = pk2(f1, f1), a2 = pk2(f2, f2), a3 = pk2(f3, f3);
            #pragma unroll
            for (int j = 0; j < 4; ++j) {
                u64 w = *reinterpret_cast<const u64*>(&Pw[kk * 260 + 64 * j + 2 * tx]);
                pacc[0][j] = f2fma(a0, w, pacc[0][j]);
                pacc[1][j] = f2fma(a1, w, pacc[1][j]);
                pacc[2][j] = f2fma(a2, w, pacc[2][j]);
                pacc[3][j] = f2fma(a3, w, pacc[3][j]);
            }
        }
        __syncthreads();
    }

    #pragma unroll
    for (int i = 0; i < 4; ++i) {
        int r = 4 * ty + i;
        if (r < nrows) {
            int hw = g_idx[b * NPTS + r0 + r];
            float* ob = out + (size_t)b * CH * HWSZ + hw;
            #pragma unroll
            for (int j = 0; j < 4; ++j) {
                int c = 64 * j + 2 * tx;
                float v0, v1; upk2(v0, v1, pacc[i][j]);
                ob[(size_t)c * HWSZ]       += v0 + pb[c];
                ob[(size_t)(c + 1) * HWSZ] += v1 + pb[c + 1];
            }
        }
    }
}

// ================= launch =================
extern "C" void kernel_launch(void* const* d_in, const int* in_sizes, int n_in,
                              void* d_out, int out_size) {
    const float* xm   = (const float*)d_in[0];
    const float* xa   = (const float*)d_in[1];
    const float* sw   = (const float*)d_in[2];
    const float* fc1w = (const float*)d_in[4];
    const float* fc1b = (const float*)d_in[5];
    const float* fc2w = (const float*)d_in[6];
    const float* fc2b = (const float*)d_in[7];
    const float* pw   = (const float*)d_in[8];
    const float* pb   = (const float*)d_in[9];
    float* out = (float*)d_out;

    const int K3_SMEM = 2 * K3_PLANE * 4 + NPAD * 4;   // 137216 B
    const int K4_SMEM = SM_TOT * 4;                    // 180736 B
    cudaFuncSetAttribute(k3_pool, cudaFuncAttributeMaxDynamicSharedMemorySize, K3_SMEM);
    cudaFuncSetAttribute(k4_attn, cudaFuncAttributeMaxDynamicSharedMemorySize, K4_SMEM);

    k1_copy_score<<<1024, 256>>>(xm, sw, out);
    k2_topk<<<BATCH, 512>>>();
    k3_pool<<<K3_GRID, 256, K3_SMEM>>>(xm, xa);
    k4_attn<<<dim3(16, BATCH), 256, K4_SMEM>>>(fc1w, fc1b, fc2w, fc2b, pw, pb, out);
}

// round 5
// speedup vs baseline: 2.0232x; 2.0232x over previous
#include <cuda_runtime.h>
#include <math_constants.h>
#include <stdint.h>

#define BATCH 8
#define CH 256
#define HH 128
#define WW 128
#define HWSZ 16384
#define NPTS 500
#define NPAD 512
#define NHID 16

typedef unsigned long long u64;

// ---------------- scratch ----------------
__device__ float g_score[BATCH * HWSZ];
__device__ float g_spart[8 * BATCH * HWSZ];
__device__ int   g_idx[BATCH * NPTS];
__device__ float g_vmt [BATCH * CH * NPAD];   // v_main transposed [b][c][n], zero-padded
__device__ float g_vat [BATCH * CH * NPAD];   // v_aux  transposed [b][c][n]
__device__ float g_vaux[BATCH * NPTS * CH];   // v_aux row-major [b][n][c]

// ---------------- f32x2 helpers ----------------
__device__ __forceinline__ u64 pk2(float x, float y) {
    u64 d; asm("mov.b64 %0, {%1, %2};" : "=l"(d) : "f"(x), "f"(y)); return d;
}
__device__ __forceinline__ void upk2(float& x, float& y, u64 d) {
    asm("mov.b64 {%0, %1}, %2;" : "=f"(x), "=f"(y) : "l"(d));
}
__device__ __forceinline__ u64 f2fma(u64 a, u64 b, u64 c) {
    u64 d; asm("fma.rn.f32x2 %0, %1, %2, %3;" : "=l"(d) : "l"(a), "l"(b), "l"(c)); return d;
}
__device__ __forceinline__ u64 f2add(u64 a, u64 b) {
    u64 d; asm("add.rn.f32x2 %0, %1, %2;" : "=l"(d) : "l"(a), "l"(b)); return d;
}

// ================= kernel 1 (round-3 version): fused copy + scorer partials =================
__global__ void k1_copy_score(const float* __restrict__ xm,
                              const float* __restrict__ sw,
                              float* __restrict__ out) {
    __shared__ float s_w[32];
    int t = threadIdx.x, chunk = blockIdx.y;
    if (t < 32) s_w[t] = sw[chunk * 32 + t];
    __syncthreads();

    int gp = (blockIdx.x * 256 + t) * 4;
    int b  = gp >> 14;
    int hw = gp & (HWSZ - 1);
    const float4* src = reinterpret_cast<const float4*>(xm + (size_t)(b * CH + chunk * 32) * HWSZ + hw);
    float4*       dst = reinterpret_cast<float4*>(out + (size_t)(b * CH + chunk * 32) * HWSZ + hw);

    float a0 = 0.f, a1 = 0.f, a2 = 0.f, a3 = 0.f;
    #pragma unroll 8
    for (int c = 0; c < 32; ++c) {
        float4 v = src[c * (HWSZ / 4)];
        dst[c * (HWSZ / 4)] = v;
        float w = s_w[c];
        a0 += v.x * w; a1 += v.y * w; a2 += v.z * w; a3 += v.w * w;
    }
    *reinterpret_cast<float4*>(g_spart + (size_t)chunk * BATCH * HWSZ + gp) =
        make_float4(a0, a1, a2, a3);
}

__global__ void k1b_reduce() {
    int i = (blockIdx.x * 256 + threadIdx.x) * 4;
    float4 s = make_float4(0.f, 0.f, 0.f, 0.f);
    #pragma unroll
    for (int ch = 0; ch < 8; ++ch) {
        float4 v = *reinterpret_cast<const float4*>(g_spart + (size_t)ch * BATCH * HWSZ + i);
        s.x += v.x; s.y += v.y; s.z += v.z; s.w += v.w;
    }
    *reinterpret_cast<float4*>(g_score + i) = s;
}

// ================= kernel 2: exact top-500 per batch via radix select =================
__global__ void k2_topk() {
    __shared__ unsigned hist[256];
    __shared__ unsigned sh_pref;
    __shared__ int sh_k;
    __shared__ int cntGT, eqcnt;
    __shared__ int eqbuf[1024];

    int b = blockIdx.x, t = threadIdx.x, bd = blockDim.x;
    const float* sc = g_score + b * HWSZ;

    unsigned prefix = 0;
    int k = NPTS;
    for (int byte = 3; byte >= 0; --byte) {
        if (t < 256) hist[t] = 0;
        __syncthreads();
        int shamt = byte * 8;
        for (int i = t; i < HWSZ; i += bd) {
            unsigned u = __float_as_uint(sc[i]);
            u = (u & 0x80000000u) ? ~u : (u | 0x80000000u);
            bool m = (byte == 3) || ((u >> (shamt + 8)) == prefix);
            if (m) atomicAdd(&hist[(u >> shamt) & 255u], 1u);
        }
        __syncthreads();
        if (t == 0) {
            int cum = 0, bin;
            for (bin = 255; bin >= 0; --bin) {
                int h = (int)hist[bin];
                if (cum + h >= k) break;
                cum += h;
            }
            if (bin < 0) bin = 0;
            sh_pref = (prefix << 8) | (unsigned)bin;
            sh_k = k - cum;
        }
        __syncthreads();
        prefix = sh_pref; k = sh_k;
        __syncthreads();
    }
    unsigned T = prefix;
    if (t == 0) { cntGT = 0; eqcnt = 0; }
    __syncthreads();
    for (int i = t; i < HWSZ; i += bd) {
        unsigned u = __float_as_uint(sc[i]);
        u = (u & 0x80000000u) ? ~u : (u | 0x80000000u);
        if (u > T) {
            int p = atomicAdd(&cntGT, 1);
            if (p < NPTS) g_idx[b * NPTS + p] = i;
        } else if (u == T) {
            int e = atomicAdd(&eqcnt, 1);
            if (e < 1024) eqbuf[e] = i;
        }
    }
    __syncthreads();
    if (t == 0) {
        int need = k;
        int base = cntGT;
        int ec = eqcnt; if (ec > 1024) ec = 1024;
        if (ec > need) {
            for (int a = 1; a < ec; ++a) {
                int v = eqbuf[a]; int jj = a - 1;
                while (jj >= 0 && eqbuf[jj] > v) { eqbuf[jj + 1] = eqbuf[jj]; --jj; }
                eqbuf[jj + 1] = v;
            }
        }
        for (int e = 0; e < need && e < ec && base + e < NPTS; ++e)
            g_idx[b * NPTS + base + e] = eqbuf[e];
    }
}

// ================= kernel 3 (round-3 version): stream plane -> pool from smem =================
__global__ void __launch_bounds__(256) k3_pool(const float* __restrict__ xm,
                                               const float* __restrict__ xa) {
    extern __shared__ float sp[];
    int* s_hw = (int*)(sp + HWSZ);
    int c = blockIdx.x, b = blockIdx.y, t = threadIdx.x;

    for (int i = t; i < NPTS; i += 256) s_hw[i] = g_idx[b * NPTS + i];

    #pragma unroll
    for (int s = 0; s < 2; ++s) {
        const float* src = (s == 0 ? xm : xa) + (size_t)(b * CH + c) * HWSZ;
        __syncthreads();
        for (int i = t; i < HWSZ / 4; i += 256)
            reinterpret_cast<float4*>(sp)[i] = reinterpret_cast<const float4*>(src)[i];
        __syncthreads();

        for (int p = t; p < NPTS; p += 256) {
            int hw = s_hw[p];
            int iy = hw >> 7, ix = hw & 127;
            float sum = 0.f, mx = -CUDART_INF_F;
            if (iy >= 3 && iy <= 124 && ix >= 3 && ix <= 124) {
                const float* base = sp + (iy - 3) * WW + (ix - 3);
                #pragma unroll
                for (int dy = 0; dy < 7; ++dy) {
                    #pragma unroll
                    for (int dx = 0; dx < 7; ++dx) {
                        float v = base[dy * WW + dx];
                        sum += v; mx = fmaxf(mx, v);
                    }
                }
            } else {
                #pragma unroll
                for (int dy = -3; dy <= 3; ++dy) {
                    int yy = iy + dy; float wy = 1.f;
                    if (yy < 0) { yy = 0; wy = 0.5f; } else if (yy > 127) { yy = 127; wy = 0.5f; }
                    #pragma unroll
                    for (int dx = -3; dx <= 3; ++dx) {
                        int xx = ix + dx; float wx = wy;
                        if (xx < 0) { xx = 0; wx *= 0.5f; } else if (xx > 127) { xx = 127; wx *= 0.5f; }
                        float v = sp[yy * WW + xx] * wx;
                        sum += v; mx = fmaxf(mx, v);
                    }
                }
            }
            float r = 0.5f * (sum * (1.f / 49.f) + mx);
            if (s == 0) {
                g_vmt[(b * CH + c) * NPAD + p] = r;
            } else {
                g_vat[(b * CH + c) * NPAD + p] = r;
                g_vaux[(b * NPTS + p) * CH + c] = r;
            }
        }
    }
}

// ================= kernel 4: 512-thread split-m attention + MLP + proj + scatter =================
// 16 warps = 2 groups of 8; group g handles m-tiles (8g+mt) in QK/PV and k-tiles in proj.
// smem (floats): Qs[256][36] @0 ; Tk[2] tiles @9216 (18432) ;
//                S_t[512][36] -> Vf_t[256][36]+W2s @27648 (18432) ; Vh[32][260] @46080 (8320)
#define SM_QS 0
#define SM_T  9216
#define SM_S  27648
#define SM_VH 46080
#define SM_TOT 54400

__global__ void __launch_bounds__(512, 1)
k4_attn(const float* __restrict__ fc1w, const float* __restrict__ fc1b,
        const float* __restrict__ fc2w, const float* __restrict__ fc2b,
        const float* __restrict__ pw,   const float* __restrict__ pb,
        float* __restrict__ out) {
    extern __shared__ float sm[];
    float* Qs  = sm + SM_QS;
    float* Tk  = sm + SM_T;
    float* S_t = sm + SM_S;
    float* Vh  = sm + SM_VH;

    const int t   = threadIdx.x;
    const int tx  = t & 31, ty = t >> 5;       // ty in [0,16)
    const int g   = ty >> 3, tyg = ty & 7;
    const int b   = blockIdx.y;
    const int r0  = blockIdx.x * 32;
    const int nrows = min(32, NPTS - r0);

    // ---- stage Q transposed tile ----
    for (int idx4 = t; idx4 < 2048; idx4 += 512) {
        int k = idx4 >> 3, i4 = (idx4 & 7) * 4;
        float4 v = *reinterpret_cast<const float4*>(&g_vmt[(b * CH + k) * NPAD + r0 + i4]);
        *reinterpret_cast<float4*>(&Qs[k * 36 + i4]) = v;
    }
    __syncthreads();

    // ---- QK: 8 iterations, two K-tiles per iteration (one per group) ----
    for (int mt = 0; mt < 8; ++mt) {
        for (int idx4 = t; idx4 < 4096; idx4 += 512) {
            int tile = idx4 >> 11;
            int k = (idx4 >> 3) & 255, i4 = (idx4 & 7) * 4;
            int m0 = (8 * tile + mt) * 32;
            float4 v = *reinterpret_cast<const float4*>(&g_vat[(b * CH + k) * NPAD + m0 + i4]);
            *reinterpret_cast<float4*>(&Tk[tile * 9216 + k * 36 + i4]) = v;
        }
        __syncthreads();
        int m0g = (8 * g + mt) * 32;
        const float* Tg = Tk + g * 9216;
        u64 s01 = pk2(0.f, 0.f), s23 = pk2(0.f, 0.f);
        #pragma unroll 8
        for (int k = 0; k < 256; ++k) {
            ulonglong2 q = *reinterpret_cast<const ulonglong2*>(&Qs[k * 36 + 4 * tyg]);
            float kk = Tg[k * 36 + tx];
            u64 kk2 = pk2(kk, kk);
            s01 = f2fma(q.x, kk2, s01);
            s23 = f2fma(q.y, kk2, s23);
        }
        float a0, a1, a2, a3;
        upk2(a0, a1, s01); upk2(a2, a3, s23);
        *reinterpret_cast<float4*>(&S_t[(m0g + tx) * 36 + 4 * tyg]) =
            make_float4(a0 * 0.0625f, a1 * 0.0625f, a2 * 0.0625f, a3 * 0.0625f);
        __syncthreads();
    }

    // ---- softmax, normalization folded into S_t (each warp owns 2 rows) ----
    #pragma unroll
    for (int i = 0; i < 2; ++i) {
        int r = 2 * ty + i;
        float mx = -CUDART_INF_F;
        for (int m = tx; m < NPTS; m += 32) mx = fmaxf(mx, S_t[m * 36 + r]);
        #pragma unroll
        for (int o = 16; o; o >>= 1) mx = fmaxf(mx, __shfl_xor_sync(0xffffffffu, mx, o));
        float sum = 0.f;
        for (int m = tx; m < NPTS; m += 32) {
            float e = __expf(S_t[m * 36 + r] - mx);
            S_t[m * 36 + r] = e;
            sum += e;
        }
        #pragma unroll
        for (int o = 16; o; o >>= 1) sum += __shfl_xor_sync(0xffffffffu, sum, o);
        float inv = 1.f / sum;
        for (int m = tx; m < NPTS; m += 32) S_t[m * 36 + r] *= inv;
    }
    __syncthreads();

    // ---- v_hat = P V, m split across groups; partial acc per group ----
    u64 acc[4][4];
    #pragma unroll
    for (int i = 0; i < 4; ++i)
        #pragma unroll
        for (int j = 0; j < 4; ++j) acc[i][j] = pk2(0.f, 0.f);

    for (int mt = 0; mt < 8; ++mt) {
        for (int idx4 = t; idx4 < 4096; idx4 += 512) {
            int tile = idx4 >> 11;
            int m = (idx4 >> 6) & 31, c4 = (idx4 & 63) * 4;
            int m0 = (8 * tile + mt) * 32;
            float4 v = make_float4(0.f, 0.f, 0.f, 0.f);
            if (m0 + m < NPTS)
                v = *reinterpret_cast<const float4*>(&g_vaux[(b * NPTS + m0 + m) * CH + c4]);
            *reinterpret_cast<float4*>(&Tk[tile * 8320 + m * 260 + c4]) = v;
        }
        __syncthreads();
        int m0g = (8 * g + mt) * 32;
        int mlim = min(32, NPTS - m0g);
        const float* Vg = Tk + g * 8320;
        for (int m = 0; m < mlim; ++m) {
            ulonglong2 pp = *reinterpret_cast<const ulonglong2*>(&S_t[(m0g + m) * 36 + 4 * tyg]);
            float p0, p1, p2, p3;
            upk2(p0, p1, pp.x); upk2(p2, p3, pp.y);
            u64 a0 = pk2(p0, p0), a1 = pk2(p1, p1), a2 = pk2(p2, p2), a3 = pk2(p3, p3);
            #pragma unroll
            for (int j = 0; j < 4; ++j) {
                u64 v = *reinterpret_cast<const u64*>(&Vg[m * 260 + 64 * j + 2 * tx]);
                acc[0][j] = f2fma(a0, v, acc[0][j]);
                acc[1][j] = f2fma(a1, v, acc[1][j]);
                acc[2][j] = f2fma(a2, v, acc[2][j]);
                acc[3][j] = f2fma(a3, v, acc[3][j]);
            }
        }
        __syncthreads();
    }
    // cross-group reduce into Vh
    if (g == 0) {
        #pragma unroll
        for (int i = 0; i < 4; ++i)
            #pragma unroll
            for (int j = 0; j < 4; ++j)
                *reinterpret_cast<u64*>(&Vh[(4 * tyg + i) * 260 + 64 * j + 2 * tx]) = acc[i][j];
    }
    __syncthreads();
    if (g == 1) {
        #pragma unroll
        for (int i = 0; i < 4; ++i)
            #pragma unroll
            for (int j = 0; j < 4; ++j) {
                u64* p = reinterpret_cast<u64*>(&Vh[(4 * tyg + i) * 260 + 64 * j + 2 * tx]);
                *p = f2add(*p, acc[i][j]);
            }
    }
    __syncthreads();

    // ---- stage MLP weights ----
    float* W1p  = Tk;                 // [256][32] interleaved (W1a,W1b)
    float* Vf_t = S_t;                // [256][36]
    float* W2s  = S_t + 9216;         // [16][256]
    for (int idx = t; idx < 256 * 16; idx += 512) {
        int k = idx >> 4, j = idx & 15;
        float wa = fc1w[idx];
        float wb = fc1w[4096 + idx];
        float wc = fc1w[8192 + idx];
        W1p[k * 32 + 2 * j]     = wa + wc;
        W1p[k * 32 + 2 * j + 1] = wb - wc;
    }
    for (int idx = t; idx < 4096; idx += 512) W2s[idx] = fc2w[idx];
    __syncthreads();

    // ---- fc1 (2 rows per warp, half-warp k-split) ----
    int jl = tx & 15, half = tx >> 4;
    float hreg[2];
    #pragma unroll
    for (int i = 0; i < 2; ++i) {
        int r = 2 * ty + i;
        u64 hp = pk2(0.f, 0.f);
        int k0 = half * 128;
        #pragma unroll 4
        for (int k = k0; k < k0 + 128; ++k) {
            float vm = Qs[k * 36 + r];
            float vh = Vh[r * 260 + k];
            u64 w = *reinterpret_cast<const u64*>(&W1p[k * 32 + 2 * jl]);
            hp = f2fma(pk2(vm, vh), w, hp);
        }
        float hx, hy; upk2(hx, hy, hp);
        float h = hx + hy;
        h += __shfl_xor_sync(0xffffffffu, h, 16);
        h += fc1b[jl];
        hreg[i] = fmaxf(h, 0.f);
    }

    // ---- fc2 + sigmoid gate + fuse; write Vf transposed [c][r] ----
    #pragma unroll
    for (int i = 0; i < 2; ++i) {
        int r = 2 * ty + i;
        for (int cb = 0; cb < 256; cb += 32) {
            int c = cb + tx;
            float gg = fc2b[c];
            #pragma unroll
            for (int jj = 0; jj < 16; ++jj) {
                float hj = __shfl_sync(0xffffffffu, hreg[i], jj);
                gg += hj * W2s[jj * 256 + c];
            }
            gg = 1.f / (1.f + __expf(-gg));
            float vm = Qs[c * 36 + r];
            float vh = Vh[r * 260 + c];
            Vf_t[c * 36 + r] = vm + gg * (vm - vh);
        }
    }
    __syncthreads();

    // ---- proj: k split across groups; two Pw tiles per iteration ----
    u64 pacc[4][4];
    #pragma unroll
    for (int i = 0; i < 4; ++i)
        #pragma unroll
        for (int j = 0; j < 4; ++j) pacc[i][j] = pk2(0.f, 0.f);

    for (int kt = 0; kt < 4; ++kt) {
        for (int idx4 = t; idx4 < 4096; idx4 += 512) {
            int tile = idx4 >> 11;
            int kk = (idx4 >> 6) & 31, c4 = (idx4 & 63) * 4;
            int k0 = (4 * tile + kt) * 32;
            float4 v = *reinterpret_cast<const float4*>(&pw[(k0 + kk) * 256 + c4]);
            *reinterpret_cast<float4*>(&Tk[tile * 8320 + kk * 260 + c4]) = v;
        }
        __syncthreads();
        int k0g = (4 * g + kt) * 32;
        const float* Pg = Tk + g * 8320;
        for (int kk = 0; kk < 32; ++kk) {
            ulonglong2 ff = *reinterpret_cast<const ulonglong2*>(&Vf_t[(k0g + kk) * 36 + 4 * tyg]);
            float f0, f1, f2, f3;
            upk2(f0, f1, ff.x); upk2(f2, f3, ff.y);
            u64 a0 = pk2(f0, f0), a1 = pk2(f1, f1), a2 = pk2(f2, f2), a3 = pk2(f3, f3);
            #pragma unroll
            for (int j = 0; j < 4; ++j) {
                u64 w = *reinterpret_cast<const u64*>(&Pg[kk * 260 + 64 * j + 2 * tx]);
                pacc[0][j] = f2fma(a0, w, pacc[0][j]);
                pacc[1][j] = f2fma(a1, w, pacc[1][j]);
                pacc[2][j] = f2fma(a2, w, pacc[2][j]);
                pacc[3][j] = f2fma(a3, w, pacc[3][j]);
            }
        }
        __syncthreads();
    }
    // cross-group reduce (Vh is dead) + scatter-add epilogue
    if (g == 0) {
        #pragma unroll
        for (int i = 0; i < 4; ++i)
            #pragma unroll
            for (int j = 0; j < 4; ++j)
                *reinterpret_cast<u64*>(&Vh[(4 * tyg + i) * 260 + 64 * j + 2 * tx]) = pacc[i][j];
    }
    __syncthreads();
    if (g == 1) {
        #pragma unroll
        for (int i = 0; i < 4; ++i) {
            int r = 4 * tyg + i;
            if (r < nrows) {
                int hw = g_idx[b * NPTS + r0 + r];
                float* ob = out + (size_t)b * CH * HWSZ + hw;
                #pragma unroll
                for (int j = 0; j < 4; ++j) {
                    int c = 64 * j + 2 * tx;
                    u64 prev = *reinterpret_cast<const u64*>(&Vh[r * 260 + c]);
                    float v0, v1; upk2(v0, v1, f2add(prev, pacc[i][j]));
                    ob[(size_t)c * HWSZ]       += v0 + pb[c];
                    ob[(size_t)(c + 1) * HWSZ] += v1 + pb[c + 1];
                }
            }
        }
    }
}

// ================= launch =================
extern "C" void kernel_launch(void* const* d_in, const int* in_sizes, int n_in,
                              void* d_out, int out_size) {
    const float* xm   = (const float*)d_in[0];
    const float* xa   = (const float*)d_in[1];
    const float* sw   = (const float*)d_in[2];
    const float* fc1w = (const float*)d_in[4];
    const float* fc1b = (const float*)d_in[5];
    const float* fc2w = (const float*)d_in[6];
    const float* fc2b = (const float*)d_in[7];
    const float* pw   = (const float*)d_in[8];
    const float* pb   = (const float*)d_in[9];
    float* out = (float*)d_out;

    const int K3_SMEM = HWSZ * 4 + NPTS * 4;   // 67536 B
    const int K4_SMEM = SM_TOT * 4;            // 217600 B
    cudaFuncSetAttribute(k3_pool, cudaFuncAttributeMaxDynamicSharedMemorySize, K3_SMEM);
    cudaFuncSetAttribute(k4_attn, cudaFuncAttributeMaxDynamicSharedMemorySize, K4_SMEM);

    k1_copy_score<<<dim3(128, 8), 256>>>(xm, sw, out);
    k1b_reduce<<<128, 256>>>();
    k2_topk<<<BATCH, 512>>>();
    k3_pool<<<dim3(CH, BATCH), 256, K3_SMEM>>>(xm, xa);
    k4_attn<<<dim3(16, BATCH), 512, K4_SMEM>>>(fc1w, fc1b, fc2w, fc2b, pw, pb, out);
}